// round 15
// baseline (speedup 1.0000x reference)
#include <cuda_runtime.h>
#include <cuda_fp16.h>
#include <math.h>
#include <stdint.h>

#define NB 4
#define NS 2048
#define ND 1024
#define NH 8
#define NK 128
#define NL 4
#define NM (NB*NS)

// ---------------- scratch ----------------------------------------------------
__device__ float  g_x  [NM*ND];
__device__ __half g_t1h[NM*ND];
__device__ __half g_x16[NM*ND];
__device__ __half g_q  [NM*ND];
__device__ __half g_k  [NM*ND];
__device__ __half g_v  [NM*ND];
__device__ __half g_ao [NM*ND];
__device__ __half g_h  [NM*ND];
__device__ __half g_wtd[12*ND*ND];
__device__ __half g_wtq[12*ND*ND];
__device__ unsigned long long g_mbits[(size_t)NB*NS*NS/64];

// ---------------- helpers ----------------------------------------------------
__device__ __forceinline__ float gelu_exact(float x) {
    return 0.5f * x * (1.0f + erff(x * 0.7071067811865476f));
}
__device__ __forceinline__ unsigned sptr(const void* p) {
    return (unsigned)__cvta_generic_to_shared(p);
}
__device__ __forceinline__ unsigned h2pack(float x, float y) {
    __half2 h = __floats2half2_rn(x, y);
    return *(unsigned*)&h;
}
__device__ __forceinline__ unsigned ex2_f16x2(float x, float y) {
    __half2 h = __floats2half2_rn(x, y);
    unsigned r;
    asm("ex2.approx.f16x2 %0, %1;" : "=r"(r) : "r"(*(unsigned*)&h));
    return r;
}
__device__ __forceinline__ void ldsm4(unsigned r[4], unsigned a) {
    asm volatile("ldmatrix.sync.aligned.m8n8.x4.shared.b16 {%0,%1,%2,%3}, [%4];\n"
        : "=r"(r[0]), "=r"(r[1]), "=r"(r[2]), "=r"(r[3]) : "r"(a));
}
__device__ __forceinline__ void ldsm4t(unsigned r[4], unsigned a) {
    asm volatile("ldmatrix.sync.aligned.m8n8.x4.trans.shared.b16 {%0,%1,%2,%3}, [%4];\n"
        : "=r"(r[0]), "=r"(r[1]), "=r"(r[2]), "=r"(r[3]) : "r"(a));
}
__device__ __forceinline__ void mma16816(float c[4], const unsigned a[4],
                                         unsigned b0, unsigned b1) {
    asm volatile("mma.sync.aligned.m16n8k16.row.col.f32.f16.f16.f32 "
        "{%0,%1,%2,%3}, {%4,%5,%6,%7}, {%8,%9}, {%0,%1,%2,%3};\n"
        : "+f"(c[0]), "+f"(c[1]), "+f"(c[2]), "+f"(c[3])
        : "r"(a[0]), "r"(a[1]), "r"(a[2]), "r"(a[3]), "r"(b0), "r"(b1));
}
#define CP16(dst, src) \
    asm volatile("cp.async.cg.shared.global [%0], [%1], 16;" :: "r"(dst), "l"(src) : "memory")
#define CP_COMMIT() asm volatile("cp.async.commit_group;" ::: "memory")

// convert-only: x f32 -> f16 (no f32 copy; layer-0 LN reads x directly)
__global__ void cvt_in(const float4* __restrict__ s, uint2* __restrict__ dh) {
    int i = blockIdx.x * blockDim.x + threadIdx.x;
    float4 v = s[i];
    uint2 hh; hh.x = h2pack(v.x, v.y); hh.y = h2pack(v.z, v.w);
    dh[i] = hh;
}

__global__ void prep_mask_bits(const int4* __restrict__ m,
                               unsigned long long* __restrict__ o) {
    size_t i = (size_t)blockIdx.x * blockDim.x + threadIdx.x;
    const int4* p = m + i * 16;
    unsigned long long bits = 0;
#pragma unroll
    for (int j = 0; j < 16; j++) {
        int4 v = p[j];
        bits |= (unsigned long long)(v.x != 0) << (j * 4 + 0);
        bits |= (unsigned long long)(v.y != 0) << (j * 4 + 1);
        bits |= (unsigned long long)(v.z != 0) << (j * 4 + 2);
        bits |= (unsigned long long)(v.w != 0) << (j * 4 + 3);
    }
    o[i] = bits;
}

// ---------------- weight transposes ------------------------------------------
__global__ void tr_dense(const float* __restrict__ wo, const float* __restrict__ w1,
                         const float* __restrict__ w2, __half* __restrict__ dst) {
    __shared__ float tile[32][33];
    int z = blockIdx.z, l = z / 3, which = z % 3;
    const float* W = (which == 0 ? wo : which == 1 ? w1 : w2) + (size_t)l * ND * ND;
    __half* D = dst + (size_t)z * ND * ND;
    int n0 = blockIdx.x * 32, k0 = blockIdx.y * 32;
    int tx = threadIdx.x, ty = threadIdx.y;
#pragma unroll
    for (int i = 0; i < 32; i += 8)
        tile[ty + i][tx] = W[(size_t)(k0 + ty + i) * ND + n0 + tx];
    __syncthreads();
#pragma unroll
    for (int i = 0; i < 32; i += 8)
        D[(size_t)(n0 + ty + i) * ND + k0 + tx] = __float2half_rn(tile[tx][ty + i]);
}

__global__ void tr_qkv(const float* __restrict__ wq, const float* __restrict__ wk,
                       const float* __restrict__ wv, __half* __restrict__ dst) {
    __shared__ float tile[32][33];
    int z = blockIdx.z;
    int l = z / 24, rem = z % 24, sel = rem / 8, h = rem % 8;
    const float* W = (sel == 0 ? wq : sel == 1 ? wk : wv) + (size_t)(l * NH + h) * ND * NK;
    __half* D = dst + (size_t)((l * 3 + sel) * 8 + h) * NK * ND;
    int n0 = blockIdx.x * 32, k0 = blockIdx.y * 32;
    int tx = threadIdx.x, ty = threadIdx.y;
#pragma unroll
    for (int i = 0; i < 32; i += 8)
        tile[ty + i][tx] = W[(size_t)(k0 + ty + i) * NK + n0 + tx];
    __syncthreads();
#pragma unroll
    for (int i = 0; i < 32; i += 8)
        D[(size_t)(n0 + ty + i) * ND + k0 + tx] = __float2half_rn(tile[tx][ty + i]);
}

// ============================================================================
// GEMM v4 (R11-proven): block 128x128, 4 warps, warp 64x64, K-chunk 32,
// 3-stage cp.async pipeline, XOR-swizzled 64B rows. All outputs f16.
// mode: 0 = plain half, 1 = half + gelu, 2 = qkv scatter
// ============================================================================
#define BK 32
#define STG 3
#define ASZ (128*BK)
#define NCH (ND/BK)
#define GEMM_SMEM_BYTES (STG*2*ASZ*2)

__global__ __launch_bounds__(128, 2) void gemm_v4(
    const __half* __restrict__ A, const __half* __restrict__ BtBase,
    const float* __restrict__ bias0, const float* __restrict__ bias1,
    const float* __restrict__ bias2,
    __half* __restrict__ Ch0, __half* __restrict__ Ch1,
    __half* __restrict__ Ch2, int mode)
{
    extern __shared__ __half smh[];
    __half* sA = smh;
    __half* sB = smh + STG * ASZ;

    const int tid = threadIdx.x, lane = tid & 31, wid = tid >> 5;
    const int wm = wid >> 1, wn = wid & 1, g = lane >> 2, t = lane & 3;
    const int m0 = blockIdx.y * 128, n0 = blockIdx.x * 128;

    const int sel = blockIdx.z;
    const __half* Bt = BtBase + (size_t)sel * ND * ND;
    const float* bias = (sel == 0) ? bias0 : (sel == 1) ? bias1 : bias2;
    __half* Ch = (sel == 0) ? Ch0 : (sel == 1) ? Ch1 : Ch2;

    float c[4][8][4];
#pragma unroll
    for (int mt = 0; mt < 4; mt++)
#pragma unroll
        for (int nt = 0; nt < 8; nt++)
#pragma unroll
            for (int i = 0; i < 4; i++) c[mt][nt][i] = 0.f;

    const int lr = tid >> 2;
    const int lu = tid & 3;
    const unsigned sA0 = sptr(sA), sB0 = sptr(sB);

    const int arow = wm * 64 + (lane & 15);
    const int axor = (arow >> 1) & 3;
    const int ahi  = lane >> 4;
    const int brow = (lane >> 4) * 8 + (lane & 7);
    const int bxor = (brow >> 1) & 3;
    const int bhi  = (lane >> 3) & 1;

#define LOAD_CHUNK(ck, st) do {                                               \
    int _k0 = (ck) * BK;                                                      \
    _Pragma("unroll")                                                         \
    for (int _i = 0; _i < 4; _i++) {                                          \
        int _r = lr + _i * 32;                                                \
        unsigned _sw = ((unsigned)(lu ^ ((_r >> 1) & 3))) * 16;               \
        CP16(sA0 + (st) * ASZ * 2 + _r * 64 + _sw,                            \
             A + (size_t)(m0 + _r) * ND + _k0 + lu * 8);                      \
        CP16(sB0 + (st) * ASZ * 2 + _r * 64 + _sw,                            \
             Bt + (size_t)(n0 + _r) * ND + _k0 + lu * 8);                     \
    }                                                                         \
    CP_COMMIT();                                                              \
} while (0)

    LOAD_CHUNK(0, 0);
    LOAD_CHUNK(1, 1);

    int st = 0;
    for (int ck = 0; ck < NCH; ck++) {
        if (ck + 2 < NCH) {
            asm volatile("cp.async.wait_group 1;" ::: "memory");
        } else {
            asm volatile("cp.async.wait_group 0;" ::: "memory");
        }
        __syncthreads();
        if (ck + 2 < NCH) {
            int st2 = st + 2; if (st2 >= STG) st2 -= STG;
            LOAD_CHUNK(ck + 2, st2);
        }

        unsigned abuf = sA0 + st * ASZ * 2;
        unsigned bbuf = sB0 + st * ASZ * 2;
#pragma unroll
        for (int ks = 0; ks < 2; ks++) {
            unsigned akoff = ((unsigned)((ks * 2 + ahi) ^ axor)) * 16;
            unsigned a[4][4];
#pragma unroll
            for (int mt = 0; mt < 4; mt++)
                ldsm4(a[mt], abuf + (arow + mt * 16) * 64 + akoff);
            unsigned bkoff = ((unsigned)((ks * 2 + bhi) ^ bxor)) * 16;
#pragma unroll
            for (int p = 0; p < 4; p++) {
                unsigned bf[4];
                ldsm4(bf, bbuf + (brow + wn * 64 + p * 16) * 64 + bkoff);
#pragma unroll
                for (int mt = 0; mt < 4; mt++) {
                    mma16816(c[mt][2 * p],     a[mt], bf[0], bf[1]);
                    mma16816(c[mt][2 * p + 1], a[mt], bf[2], bf[3]);
                }
            }
        }
        if (++st >= STG) st -= STG;
    }

#pragma unroll
    for (int mt = 0; mt < 4; mt++) {
        int r0 = m0 + wm * 64 + mt * 16 + g;
#pragma unroll
        for (int nt = 0; nt < 8; nt++) {
            int col = n0 + wn * 64 + nt * 8 + 2 * t;
            float b0 = bias[col], b1 = bias[col + 1];
            float v0 = c[mt][nt][0] + b0, v1 = c[mt][nt][1] + b1;
            float v2 = c[mt][nt][2] + b0, v3 = c[mt][nt][3] + b1;
            if (mode == 1) {
                v0 = gelu_exact(v0); v1 = gelu_exact(v1);
                v2 = gelu_exact(v2); v3 = gelu_exact(v3);
            }
            if (mode == 2) {
                int head = col >> 7, within = col & 127;
                int bb0 = r0 >> 11, s0 = r0 & (NS - 1);
                __half* d0 = Ch + ((size_t)(bb0 * NH + head) * NS + s0) * NK + within;
                *(unsigned*)(d0)          = h2pack(v0, v1);
                *(unsigned*)(d0 + 8 * NK) = h2pack(v2, v3);
            } else {
                *(unsigned*)(Ch + (size_t)r0 * ND + col)       = h2pack(v0, v1);
                *(unsigned*)(Ch + (size_t)(r0 + 8) * ND + col) = h2pack(v2, v3);
            }
        }
    }
}

// ============================================================================
// Flash attention (R11-proven + rescale-skip): 8 warps x (16 rows x 64 cols),
// register P, Q in registers, K/V double-buffered cp.async, ONE barrier/tile,
// f16x2 exp, bitmask mask.
// ============================================================================
#define QS_STR 136
#define KS_STR 136
#define VS_STR 136
#define AOFF_Q 0
#define AOFF_K (128*QS_STR)
#define AOFF_V (AOFF_K + 2*64*KS_STR)
#define ATTN_SMEM_BYTES ((AOFF_V + 2*64*VS_STR)*2)
#define MW (NS/64)

__global__ __launch_bounds__(256) void attn_f16(
    const __half* __restrict__ Qg, const __half* __restrict__ Kg,
    const __half* __restrict__ Vg, const unsigned long long* __restrict__ Mb,
    __half* __restrict__ Og)
{
    extern __shared__ __half smh[];
    const int tid = threadIdx.x, lane = tid & 31, w = tid >> 5;
    const int g = lane >> 2, t = lane & 3;
    const int bh = blockIdx.y, b = bh >> 3, h = bh & 7;
    const int q0 = blockIdx.x * 128;
    const unsigned smb = sptr(smh);

#define ATTN_LOAD_KV(tnext, buf) do {                                         \
    const __half* _Kb = Kg + ((size_t)bh * NS + (tnext)) * NK;                \
    const __half* _Vb = Vg + ((size_t)bh * NS + (tnext)) * NK;                \
    _Pragma("unroll")                                                         \
    for (int _i = 0; _i < 4; _i++) {                                          \
        int _u = tid + _i * 256;                                              \
        int _r = _u >> 4, _c = (_u & 15) * 8;                                 \
        CP16(smb + (AOFF_K + (buf) * 64 * KS_STR + _r * KS_STR + _c) * 2,     \
             _Kb + _r * NK + _c);                                             \
        CP16(smb + (AOFF_V + (buf) * 64 * VS_STR + _r * VS_STR + _c) * 2,     \
             _Vb + _r * NK + _c);                                             \
    }                                                                         \
    CP_COMMIT();                                                              \
} while (0)

    ATTN_LOAD_KV(0, 0);

    const __half* Qb = Qg + ((size_t)bh * NS + q0) * NK;
#pragma unroll
    for (int i = 0; i < 8; i++) {
        int idx = tid + i * 256;
        int r = idx >> 4, c8 = (idx & 15) * 8;
        *(uint4*)&smh[AOFF_Q + r * QS_STR + c8] = *(const uint4*)(Qb + (size_t)r * NK + c8);
    }
    __syncthreads();

    unsigned qf[8][4];
    {
        unsigned qbase = smb + (AOFF_Q + (w * 16 + (lane & 15)) * QS_STR + (lane >> 4) * 8) * 2;
#pragma unroll
        for (int ks = 0; ks < 8; ks++) ldsm4(qf[ks], qbase + ks * 32);
    }

    float accz[16][4];
#pragma unroll
    for (int nt = 0; nt < 16; nt++)
#pragma unroll
        for (int i = 0; i < 4; i++) accz[nt][i] = 0.f;

    float m0 = -INFINITY, m1 = -INFINITY, l0 = 0.f, l1 = 0.f;
    const float scale = 0.08838834764831845f;
    const float LOG2E = 1.4426950408889634f;

    const int rl = w * 16 + g;
    const unsigned long long* mb0 = Mb + ((size_t)b * NS + q0 + rl) * MW;
    const unsigned long long* mb1 = mb0 + 8 * MW;

    for (int tix = 0; tix < NS / 64; tix++) {
        const int buf = tix & 1;

        const unsigned long long mk0 = mb0[tix];
        const unsigned long long mk1 = mb1[tix];

        asm volatile("cp.async.wait_group 0;" ::: "memory");
        __syncthreads();
        if (tix + 1 < NS / 64) ATTN_LOAD_KV((tix + 1) * 64, buf ^ 1);

        float sc[8][4];
#pragma unroll
        for (int nt = 0; nt < 8; nt++)
#pragma unroll
            for (int i = 0; i < 4; i++) sc[nt][i] = 0.f;
        {
            unsigned kbase = smb + (AOFF_K + buf * 64 * KS_STR +
                ((lane >> 4) * 8 + (lane & 7)) * KS_STR + ((lane >> 3) & 1) * 8) * 2;
#pragma unroll
            for (int ks = 0; ks < 8; ks++) {
                unsigned kb[4][4];
#pragma unroll
                for (int p = 0; p < 4; p++)
                    ldsm4(kb[p], kbase + p * 16 * KS_STR * 2 + ks * 32);
#pragma unroll
                for (int p = 0; p < 4; p++) {
                    mma16816(sc[2 * p],     qf[ks], kb[p][0], kb[p][1]);
                    mma16816(sc[2 * p + 1], qf[ks], kb[p][2], kb[p][3]);
                }
            }
        }

        float tm0 = -INFINITY, tm1 = -INFINITY;
#pragma unroll
        for (int nt = 0; nt < 8; nt++) {
            const int sh = nt * 8 + 2 * t;
            float s0 = ((mk0 >> sh) & 1ull)       ? sc[nt][0] * scale : -1.0e9f;
            float s1 = ((mk0 >> (sh + 1)) & 1ull) ? sc[nt][1] * scale : -1.0e9f;
            float s2 = ((mk1 >> sh) & 1ull)       ? sc[nt][2] * scale : -1.0e9f;
            float s3 = ((mk1 >> (sh + 1)) & 1ull) ? sc[nt][3] * scale : -1.0e9f;
            sc[nt][0] = s0; sc[nt][1] = s1; sc[nt][2] = s2; sc[nt][3] = s3;
            tm0 = fmaxf(tm0, fmaxf(s0, s1));
            tm1 = fmaxf(tm1, fmaxf(s2, s3));
        }
        tm0 = fmaxf(tm0, __shfl_xor_sync(0xffffffffu, tm0, 1));
        tm0 = fmaxf(tm0, __shfl_xor_sync(0xffffffffu, tm0, 2));
        tm1 = fmaxf(tm1, __shfl_xor_sync(0xffffffffu, tm1, 1));
        tm1 = fmaxf(tm1, __shfl_xor_sync(0xffffffffu, tm1, 2));

        float mn0 = fmaxf(m0, tm0), mn1 = fmaxf(m1, tm1);
        // warp-uniform skip of accz rescale when no row updated its max
        bool need = (mn0 != m0) || (mn1 != m1);
        if (__any_sync(0xffffffffu, need)) {
            float c0 = __expf(m0 - mn0), c1 = __expf(m1 - mn1);
            l0 *= c0; l1 *= c1;
#pragma unroll
            for (int nt = 0; nt < 16; nt++) {
                accz[nt][0] *= c0; accz[nt][1] *= c0;
                accz[nt][2] *= c1; accz[nt][3] *= c1;
            }
        }
        m0 = mn0; m1 = mn1;

        const float b0l = mn0 * LOG2E, b1l = mn1 * LOG2E;
        unsigned pf[4][4];
#pragma unroll
        for (int nt = 0; nt < 8; nt++) {
            float x0 = fmaf(sc[nt][0], LOG2E, -b0l);
            float x1 = fmaf(sc[nt][1], LOG2E, -b0l);
            float x2 = fmaf(sc[nt][2], LOG2E, -b1l);
            float x3 = fmaf(sc[nt][3], LOG2E, -b1l);
            unsigned e01 = ex2_f16x2(x0, x1);
            unsigned e23 = ex2_f16x2(x2, x3);
            float2 f01 = __half22float2(*(__half2*)&e01);
            float2 f23 = __half22float2(*(__half2*)&e23);
            l0 += f01.x + f01.y;
            l1 += f23.x + f23.y;
            pf[nt >> 1][(nt & 1) * 2 + 0] = e01;
            pf[nt >> 1][(nt & 1) * 2 + 1] = e23;
        }

        {
            unsigned vbase = smb + (AOFF_V + buf * 64 * VS_STR +
                (lane & 15) * VS_STR + (lane >> 4) * 8) * 2;
#pragma unroll
            for (int kt = 0; kt < 4; kt++) {
#pragma unroll
                for (int p = 0; p < 8; p++) {
                    unsigned vf[4];
                    ldsm4t(vf, vbase + kt * 16 * VS_STR * 2 + p * 32);
                    mma16816(accz[2 * p],     pf[kt], vf[0], vf[1]);
                    mma16816(accz[2 * p + 1], pf[kt], vf[2], vf[3]);
                }
            }
        }
    }

    l0 += __shfl_xor_sync(0xffffffffu, l0, 1);
    l0 += __shfl_xor_sync(0xffffffffu, l0, 2);
    l1 += __shfl_xor_sync(0xffffffffu, l1, 1);
    l1 += __shfl_xor_sync(0xffffffffu, l1, 2);
    float inv0 = 1.0f / l0, inv1 = 1.0f / l1;

    const int row0 = q0 + w * 16 + g;
#pragma unroll
    for (int nt = 0; nt < 16; nt++) {
        int col = nt * 8 + 2 * t;
        __half* d0 = Og + ((size_t)(b * NS + row0)) * ND + h * NK + col;
        *(unsigned*)(d0)          = h2pack(accz[nt][0] * inv0, accz[nt][1] * inv0);
        *(unsigned*)(d0 + 8 * ND) = h2pack(accz[nt][2] * inv1, accz[nt][3] * inv1);
    }
}

// ---------------- fused residual add + LayerNorm (R now f16) ----------------
__global__ __launch_bounds__(256) void add_ln_kernel(
    const float* __restrict__ X, const __half* __restrict__ R,
    const float* __restrict__ ga, const float* __restrict__ be,
    float* __restrict__ O, __half* __restrict__ O16)
{
    __shared__ float red1[8];
    __shared__ float red2[8];
    __shared__ float s_mean, s_rstd;
    const int row = blockIdx.x;
    const int tid = threadIdx.x;
    const size_t base = (size_t)row * ND;

    float4 a = *(const float4*)(X + base + tid * 4);
    uint2 rr = *(const uint2*)(R + base + tid * 4);
    float2 ra = __half22float2(*(__half2*)&rr.x);
    float2 rb = __half22float2(*(__half2*)&rr.y);
    float v0 = a.x + ra.x, v1 = a.y + ra.y, v2 = a.z + rb.x, v3 = a.w + rb.y;

    float s = v0 + v1 + v2 + v3;
#pragma unroll
    for (int o = 16; o > 0; o >>= 1) s += __shfl_xor_sync(0xffffffffu, s, o);
    if ((tid & 31) == 0) red1[tid >> 5] = s;
    __syncthreads();
    if (tid == 0) {
        float tt = 0.f;
#pragma unroll
        for (int i = 0; i < 8; i++) tt += red1[i];
        s_mean = tt * (1.0f / ND);
    }
    __syncthreads();
    const float mean = s_mean;
    float d0 = v0 - mean, d1 = v1 - mean, d2 = v2 - mean, d3 = v3 - mean;
    float q = d0 * d0 + d1 * d1 + d2 * d2 + d3 * d3;
#pragma unroll
    for (int o = 16; o > 0; o >>= 1) q += __shfl_xor_sync(0xffffffffu, q, o);
    if ((tid & 31) == 0) red2[tid >> 5] = q;
    __syncthreads();
    if (tid == 0) {
        float tt = 0.f;
#pragma unroll
        for (int i = 0; i < 8; i++) tt += red2[i];
        s_rstd = rsqrtf(tt * (1.0f / ND) + 1e-5f);
    }
    __syncthreads();
    const float rstd = s_rstd;

    float4 g4 = *(const float4*)(ga + tid * 4);
    float4 b4 = *(const float4*)(be + tid * 4);
    float4 o4;
    o4.x = d0 * rstd * g4.x + b4.x;
    o4.y = d1 * rstd * g4.y + b4.y;
    o4.z = d2 * rstd * g4.z + b4.z;
    o4.w = d3 * rstd * g4.w + b4.w;
    *(float4*)(O + base + tid * 4) = o4;
    uint2 hh; hh.x = h2pack(o4.x, o4.y); hh.y = h2pack(o4.z, o4.w);
    *(uint2*)(O16 + base + tid * 4) = hh;
}

// ---------------- launcher ---------------------------------------------------
extern "C" void kernel_launch(void* const* d_in, const int* in_sizes, int n_in,
                              void* d_out, int out_size) {
    (void)in_sizes; (void)n_in; (void)out_size;
    const float* x    = (const float*)d_in[0];
    const int*   mask = (const int*)  d_in[1];
    const float* wq   = (const float*)d_in[2];
    const float* bq   = (const float*)d_in[3];
    const float* wk   = (const float*)d_in[4];
    const float* bk   = (const float*)d_in[5];
    const float* wv   = (const float*)d_in[6];
    const float* bv   = (const float*)d_in[7];
    const float* wo   = (const float*)d_in[8];
    const float* bo   = (const float*)d_in[9];
    const float* w1   = (const float*)d_in[10];
    const float* b1   = (const float*)d_in[11];
    const float* w2   = (const float*)d_in[12];
    const float* b2   = (const float*)d_in[13];
    const float* l1g  = (const float*)d_in[14];
    const float* l1b  = (const float*)d_in[15];
    const float* l2g  = (const float*)d_in[16];
    const float* l2b  = (const float*)d_in[17];

    float *px;
    __half *pt1h, *px16, *pq, *pk, *pv, *pao, *ph, *pwtd, *pwtq;
    unsigned long long* pmb;
    cudaGetSymbolAddress((void**)&px,   g_x);
    cudaGetSymbolAddress((void**)&pt1h, g_t1h);
    cudaGetSymbolAddress((void**)&px16, g_x16);
    cudaGetSymbolAddress((void**)&pq,   g_q);
    cudaGetSymbolAddress((void**)&pk,   g_k);
    cudaGetSymbolAddress((void**)&pv,   g_v);
    cudaGetSymbolAddress((void**)&pao,  g_ao);
    cudaGetSymbolAddress((void**)&ph,   g_h);
    cudaGetSymbolAddress((void**)&pwtd, g_wtd);
    cudaGetSymbolAddress((void**)&pwtq, g_wtq);
    cudaGetSymbolAddress((void**)&pmb,  g_mbits);

    cudaFuncSetAttribute(gemm_v4, cudaFuncAttributeMaxDynamicSharedMemorySize, GEMM_SMEM_BYTES);
    cudaFuncSetAttribute(attn_f16, cudaFuncAttributeMaxDynamicSharedMemorySize, ATTN_SMEM_BYTES);

    tr_dense<<<dim3(32, 32, 12), dim3(32, 8)>>>(wo, w1, w2, pwtd);
    tr_qkv  <<<dim3(4,  32, 96), dim3(32, 8)>>>(wq, wk, wv, pwtq);
    prep_mask_bits<<<((size_t)NB * NS * NS / 64) / 256, 256>>>((const int4*)mask, pmb);

    cvt_in<<<(NM * ND / 4) / 256, 256>>>((const float4*)x, (uint2*)px16);

    const dim3 ggrid(ND / 128, NM / 128);
    const dim3 gqkv (ND / 128, NM / 128, 3);

    for (int l = 0; l < NL; l++) {
        const size_t vof = (size_t)l * ND;
        const size_t qb  = (size_t)l * NH * NK;

        gemm_v4<<<gqkv, 128, GEMM_SMEM_BYTES>>>(
            px16, pwtq + (size_t)l * 3 * ND * ND,
            bq + qb, bk + qb, bv + qb,
            pq, pk, pv, 2);

        attn_f16<<<dim3(NS / 128, NB * NH), 256, ATTN_SMEM_BYTES>>>(
            pq, pk, pv, pmb, pao);

        gemm_v4<<<ggrid, 128, GEMM_SMEM_BYTES>>>(
            pao, pwtd + (size_t)(l * 3 + 0) * ND * ND,
            bo + vof, (float*)0, (float*)0, pt1h, (__half*)0, (__half*)0, 0);
        // layer 0 reads the original f32 input directly (no copy)
        add_ln_kernel<<<NM, 256>>>((l == 0) ? x : px, pt1h,
                                   l1g + vof, l1b + vof, px, px16);

        gemm_v4<<<ggrid, 128, GEMM_SMEM_BYTES>>>(
            px16, pwtd + (size_t)(l * 3 + 1) * ND * ND,
            b1 + vof, (float*)0, (float*)0, ph, (__half*)0, (__half*)0, 1);
        gemm_v4<<<ggrid, 128, GEMM_SMEM_BYTES>>>(
            ph, pwtd + (size_t)(l * 3 + 2) * ND * ND,
            b2 + vof, (float*)0, (float*)0, pt1h, (__half*)0, (__half*)0, 0);

        float* dst = (l == NL - 1) ? (float*)d_out : px;
        add_ln_kernel<<<NM, 256>>>(px, pt1h, l2g + vof, l2b + vof, dst, px16);
    }
}

// round 16
// speedup vs baseline: 1.0514x; 1.0514x over previous
#include <cuda_runtime.h>
#include <cuda_fp16.h>
#include <math.h>
#include <stdint.h>

#define NB 4
#define NS 2048
#define ND 1024
#define NH 8
#define NK 128
#define NL 4
#define NM (NB*NS)

// ---------------- scratch ----------------------------------------------------
__device__ float  g_x  [NM*ND];
__device__ __half g_t1h[NM*ND];
__device__ __half g_x16[NM*ND];
__device__ __half g_q  [NM*ND];
__device__ __half g_k  [NM*ND];
__device__ __half g_v  [NM*ND];
__device__ __half g_ao [NM*ND];
__device__ __half g_h  [NM*ND];
__device__ __half g_wtd[12*ND*ND];
__device__ __half g_wtq[12*ND*ND];
__device__ unsigned long long g_mbits[(size_t)NB*NS*NS/64];

// ---------------- helpers ----------------------------------------------------
__device__ __forceinline__ float gelu_exact(float x) {
    return 0.5f * x * (1.0f + erff(x * 0.7071067811865476f));
}
__device__ __forceinline__ unsigned sptr(const void* p) {
    return (unsigned)__cvta_generic_to_shared(p);
}
__device__ __forceinline__ unsigned h2pack(float x, float y) {
    __half2 h = __floats2half2_rn(x, y);
    return *(unsigned*)&h;
}
__device__ __forceinline__ unsigned ex2_f16x2(float x, float y) {
    __half2 h = __floats2half2_rn(x, y);
    unsigned r;
    asm("ex2.approx.f16x2 %0, %1;" : "=r"(r) : "r"(*(unsigned*)&h));
    return r;
}
__device__ __forceinline__ void ldsm4(unsigned r[4], unsigned a) {
    asm volatile("ldmatrix.sync.aligned.m8n8.x4.shared.b16 {%0,%1,%2,%3}, [%4];\n"
        : "=r"(r[0]), "=r"(r[1]), "=r"(r[2]), "=r"(r[3]) : "r"(a));
}
__device__ __forceinline__ void ldsm4t(unsigned r[4], unsigned a) {
    asm volatile("ldmatrix.sync.aligned.m8n8.x4.trans.shared.b16 {%0,%1,%2,%3}, [%4];\n"
        : "=r"(r[0]), "=r"(r[1]), "=r"(r[2]), "=r"(r[3]) : "r"(a));
}
__device__ __forceinline__ void mma16816(float c[4], const unsigned a[4],
                                         unsigned b0, unsigned b1) {
    asm volatile("mma.sync.aligned.m16n8k16.row.col.f32.f16.f16.f32 "
        "{%0,%1,%2,%3}, {%4,%5,%6,%7}, {%8,%9}, {%0,%1,%2,%3};\n"
        : "+f"(c[0]), "+f"(c[1]), "+f"(c[2]), "+f"(c[3])
        : "r"(a[0]), "r"(a[1]), "r"(a[2]), "r"(a[3]), "r"(b0), "r"(b1));
}
#define CP16(dst, src) \
    asm volatile("cp.async.cg.shared.global [%0], [%1], 16;" :: "r"(dst), "l"(src) : "memory")
#define CP_COMMIT() asm volatile("cp.async.commit_group;" ::: "memory")

// convert-only: x f32 -> f16 (layer-0 LN reads x directly)
__global__ void cvt_in(const float4* __restrict__ s, uint2* __restrict__ dh) {
    int i = blockIdx.x * blockDim.x + threadIdx.x;
    float4 v = s[i];
    uint2 hh; hh.x = h2pack(v.x, v.y); hh.y = h2pack(v.z, v.w);
    dh[i] = hh;
}

__global__ void prep_mask_bits(const int4* __restrict__ m,
                               unsigned long long* __restrict__ o) {
    size_t i = (size_t)blockIdx.x * blockDim.x + threadIdx.x;
    const int4* p = m + i * 16;
    unsigned long long bits = 0;
#pragma unroll
    for (int j = 0; j < 16; j++) {
        int4 v = p[j];
        bits |= (unsigned long long)(v.x != 0) << (j * 4 + 0);
        bits |= (unsigned long long)(v.y != 0) << (j * 4 + 1);
        bits |= (unsigned long long)(v.z != 0) << (j * 4 + 2);
        bits |= (unsigned long long)(v.w != 0) << (j * 4 + 3);
    }
    o[i] = bits;
}

// ---------------- weight transposes ------------------------------------------
__global__ void tr_dense(const float* __restrict__ wo, const float* __restrict__ w1,
                         const float* __restrict__ w2, __half* __restrict__ dst) {
    __shared__ float tile[32][33];
    int z = blockIdx.z, l = z / 3, which = z % 3;
    const float* W = (which == 0 ? wo : which == 1 ? w1 : w2) + (size_t)l * ND * ND;
    __half* D = dst + (size_t)z * ND * ND;
    int n0 = blockIdx.x * 32, k0 = blockIdx.y * 32;
    int tx = threadIdx.x, ty = threadIdx.y;
#pragma unroll
    for (int i = 0; i < 32; i += 8)
        tile[ty + i][tx] = W[(size_t)(k0 + ty + i) * ND + n0 + tx];
    __syncthreads();
#pragma unroll
    for (int i = 0; i < 32; i += 8)
        D[(size_t)(n0 + ty + i) * ND + k0 + tx] = __float2half_rn(tile[tx][ty + i]);
}

__global__ void tr_qkv(const float* __restrict__ wq, const float* __restrict__ wk,
                       const float* __restrict__ wv, __half* __restrict__ dst) {
    __shared__ float tile[32][33];
    int z = blockIdx.z;
    int l = z / 24, rem = z % 24, sel = rem / 8, h = rem % 8;
    const float* W = (sel == 0 ? wq : sel == 1 ? wk : wv) + (size_t)(l * NH + h) * ND * NK;
    __half* D = dst + (size_t)((l * 3 + sel) * 8 + h) * NK * ND;
    int n0 = blockIdx.x * 32, k0 = blockIdx.y * 32;
    int tx = threadIdx.x, ty = threadIdx.y;
#pragma unroll
    for (int i = 0; i < 32; i += 8)
        tile[ty + i][tx] = W[(size_t)(k0 + ty + i) * NK + n0 + tx];
    __syncthreads();
#pragma unroll
    for (int i = 0; i < 32; i += 8)
        D[(size_t)(n0 + ty + i) * ND + k0 + tx] = __float2half_rn(tile[tx][ty + i]);
}

// ============================================================================
// GEMM v4 (R11-proven): block 128x128, 4 warps, warp 64x64, K-chunk 32,
// 3-stage cp.async pipeline, XOR-swizzled 64B rows. All outputs f16.
// mode: 0 = plain half, 1 = half + gelu, 2 = qkv scatter
// ============================================================================
#define BK 32
#define STG 3
#define ASZ (128*BK)
#define NCH (ND/BK)
#define GEMM_SMEM_BYTES (STG*2*ASZ*2)

__global__ __launch_bounds__(128, 2) void gemm_v4(
    const __half* __restrict__ A, const __half* __restrict__ BtBase,
    const float* __restrict__ bias0, const float* __restrict__ bias1,
    const float* __restrict__ bias2,
    __half* __restrict__ Ch0, __half* __restrict__ Ch1,
    __half* __restrict__ Ch2, int mode)
{
    extern __shared__ __half smh[];
    __half* sA = smh;
    __half* sB = smh + STG * ASZ;

    const int tid = threadIdx.x, lane = tid & 31, wid = tid >> 5;
    const int wm = wid >> 1, wn = wid & 1, g = lane >> 2, t = lane & 3;
    const int m0 = blockIdx.y * 128, n0 = blockIdx.x * 128;

    const int sel = blockIdx.z;
    const __half* Bt = BtBase + (size_t)sel * ND * ND;
    const float* bias = (sel == 0) ? bias0 : (sel == 1) ? bias1 : bias2;
    __half* Ch = (sel == 0) ? Ch0 : (sel == 1) ? Ch1 : Ch2;

    float c[4][8][4];
#pragma unroll
    for (int mt = 0; mt < 4; mt++)
#pragma unroll
        for (int nt = 0; nt < 8; nt++)
#pragma unroll
            for (int i = 0; i < 4; i++) c[mt][nt][i] = 0.f;

    const int lr = tid >> 2;
    const int lu = tid & 3;
    const unsigned sA0 = sptr(sA), sB0 = sptr(sB);

    const int arow = wm * 64 + (lane & 15);
    const int axor = (arow >> 1) & 3;
    const int ahi  = lane >> 4;
    const int brow = (lane >> 4) * 8 + (lane & 7);
    const int bxor = (brow >> 1) & 3;
    const int bhi  = (lane >> 3) & 1;

#define LOAD_CHUNK(ck, st) do {                                               \
    int _k0 = (ck) * BK;                                                      \
    _Pragma("unroll")                                                         \
    for (int _i = 0; _i < 4; _i++) {                                          \
        int _r = lr + _i * 32;                                                \
        unsigned _sw = ((unsigned)(lu ^ ((_r >> 1) & 3))) * 16;               \
        CP16(sA0 + (st) * ASZ * 2 + _r * 64 + _sw,                            \
             A + (size_t)(m0 + _r) * ND + _k0 + lu * 8);                      \
        CP16(sB0 + (st) * ASZ * 2 + _r * 64 + _sw,                            \
             Bt + (size_t)(n0 + _r) * ND + _k0 + lu * 8);                     \
    }                                                                         \
    CP_COMMIT();                                                              \
} while (0)

    LOAD_CHUNK(0, 0);
    LOAD_CHUNK(1, 1);

    int st = 0;
    for (int ck = 0; ck < NCH; ck++) {
        if (ck + 2 < NCH) {
            asm volatile("cp.async.wait_group 1;" ::: "memory");
        } else {
            asm volatile("cp.async.wait_group 0;" ::: "memory");
        }
        __syncthreads();
        if (ck + 2 < NCH) {
            int st2 = st + 2; if (st2 >= STG) st2 -= STG;
            LOAD_CHUNK(ck + 2, st2);
        }

        unsigned abuf = sA0 + st * ASZ * 2;
        unsigned bbuf = sB0 + st * ASZ * 2;
#pragma unroll
        for (int ks = 0; ks < 2; ks++) {
            unsigned akoff = ((unsigned)((ks * 2 + ahi) ^ axor)) * 16;
            unsigned a[4][4];
#pragma unroll
            for (int mt = 0; mt < 4; mt++)
                ldsm4(a[mt], abuf + (arow + mt * 16) * 64 + akoff);
            unsigned bkoff = ((unsigned)((ks * 2 + bhi) ^ bxor)) * 16;
#pragma unroll
            for (int p = 0; p < 4; p++) {
                unsigned bf[4];
                ldsm4(bf, bbuf + (brow + wn * 64 + p * 16) * 64 + bkoff);
#pragma unroll
                for (int mt = 0; mt < 4; mt++) {
                    mma16816(c[mt][2 * p],     a[mt], bf[0], bf[1]);
                    mma16816(c[mt][2 * p + 1], a[mt], bf[2], bf[3]);
                }
            }
        }
        if (++st >= STG) st -= STG;
    }

#pragma unroll
    for (int mt = 0; mt < 4; mt++) {
        int r0 = m0 + wm * 64 + mt * 16 + g;
#pragma unroll
        for (int nt = 0; nt < 8; nt++) {
            int col = n0 + wn * 64 + nt * 8 + 2 * t;
            float b0 = bias[col], b1 = bias[col + 1];
            float v0 = c[mt][nt][0] + b0, v1 = c[mt][nt][1] + b1;
            float v2 = c[mt][nt][2] + b0, v3 = c[mt][nt][3] + b1;
            if (mode == 1) {
                v0 = gelu_exact(v0); v1 = gelu_exact(v1);
                v2 = gelu_exact(v2); v3 = gelu_exact(v3);
            }
            if (mode == 2) {
                int head = col >> 7, within = col & 127;
                int bb0 = r0 >> 11, s0 = r0 & (NS - 1);
                __half* d0 = Ch + ((size_t)(bb0 * NH + head) * NS + s0) * NK + within;
                *(unsigned*)(d0)          = h2pack(v0, v1);
                *(unsigned*)(d0 + 8 * NK) = h2pack(v2, v3);
            } else {
                *(unsigned*)(Ch + (size_t)r0 * ND + col)       = h2pack(v0, v1);
                *(unsigned*)(Ch + (size_t)(r0 + 8) * ND + col) = h2pack(v2, v3);
            }
        }
    }
}

// ============================================================================
// Flash attention (R11-proven, unconditional rescale): 8 warps x (16x64),
// register P, Q in registers, K/V double-buffered cp.async, ONE barrier/tile,
// f16x2 exp, bitmask mask.
// ============================================================================
#define QS_STR 136
#define KS_STR 136
#define VS_STR 136
#define AOFF_Q 0
#define AOFF_K (128*QS_STR)
#define AOFF_V (AOFF_K + 2*64*KS_STR)
#define ATTN_SMEM_BYTES ((AOFF_V + 2*64*VS_STR)*2)
#define MW (NS/64)

__global__ __launch_bounds__(256) void attn_f16(
    const __half* __restrict__ Qg, const __half* __restrict__ Kg,
    const __half* __restrict__ Vg, const unsigned long long* __restrict__ Mb,
    __half* __restrict__ Og)
{
    extern __shared__ __half smh[];
    const int tid = threadIdx.x, lane = tid & 31, w = tid >> 5;
    const int g = lane >> 2, t = lane & 3;
    const int bh = blockIdx.y, b = bh >> 3, h = bh & 7;
    const int q0 = blockIdx.x * 128;
    const unsigned smb = sptr(smh);

#define ATTN_LOAD_KV(tnext, buf) do {                                         \
    const __half* _Kb = Kg + ((size_t)bh * NS + (tnext)) * NK;                \
    const __half* _Vb = Vg + ((size_t)bh * NS + (tnext)) * NK;                \
    _Pragma("unroll")                                                         \
    for (int _i = 0; _i < 4; _i++) {                                          \
        int _u = tid + _i * 256;                                              \
        int _r = _u >> 4, _c = (_u & 15) * 8;                                 \
        CP16(smb + (AOFF_K + (buf) * 64 * KS_STR + _r * KS_STR + _c) * 2,     \
             _Kb + _r * NK + _c);                                             \
        CP16(smb + (AOFF_V + (buf) * 64 * VS_STR + _r * VS_STR + _c) * 2,     \
             _Vb + _r * NK + _c);                                             \
    }                                                                         \
    CP_COMMIT();                                                              \
} while (0)

    ATTN_LOAD_KV(0, 0);

    const __half* Qb = Qg + ((size_t)bh * NS + q0) * NK;
#pragma unroll
    for (int i = 0; i < 8; i++) {
        int idx = tid + i * 256;
        int r = idx >> 4, c8 = (idx & 15) * 8;
        *(uint4*)&smh[AOFF_Q + r * QS_STR + c8] = *(const uint4*)(Qb + (size_t)r * NK + c8);
    }
    __syncthreads();

    unsigned qf[8][4];
    {
        unsigned qbase = smb + (AOFF_Q + (w * 16 + (lane & 15)) * QS_STR + (lane >> 4) * 8) * 2;
#pragma unroll
        for (int ks = 0; ks < 8; ks++) ldsm4(qf[ks], qbase + ks * 32);
    }

    float accz[16][4];
#pragma unroll
    for (int nt = 0; nt < 16; nt++)
#pragma unroll
        for (int i = 0; i < 4; i++) accz[nt][i] = 0.f;

    float m0 = -INFINITY, m1 = -INFINITY, l0 = 0.f, l1 = 0.f;
    const float scale = 0.08838834764831845f;
    const float LOG2E = 1.4426950408889634f;

    const int rl = w * 16 + g;
    const unsigned long long* mb0 = Mb + ((size_t)b * NS + q0 + rl) * MW;
    const unsigned long long* mb1 = mb0 + 8 * MW;

    for (int tix = 0; tix < NS / 64; tix++) {
        const int buf = tix & 1;

        const unsigned long long mk0 = mb0[tix];
        const unsigned long long mk1 = mb1[tix];

        asm volatile("cp.async.wait_group 0;" ::: "memory");
        __syncthreads();
        if (tix + 1 < NS / 64) ATTN_LOAD_KV((tix + 1) * 64, buf ^ 1);

        float sc[8][4];
#pragma unroll
        for (int nt = 0; nt < 8; nt++)
#pragma unroll
            for (int i = 0; i < 4; i++) sc[nt][i] = 0.f;
        {
            unsigned kbase = smb + (AOFF_K + buf * 64 * KS_STR +
                ((lane >> 4) * 8 + (lane & 7)) * KS_STR + ((lane >> 3) & 1) * 8) * 2;
#pragma unroll
            for (int ks = 0; ks < 8; ks++) {
                unsigned kb[4][4];
#pragma unroll
                for (int p = 0; p < 4; p++)
                    ldsm4(kb[p], kbase + p * 16 * KS_STR * 2 + ks * 32);
#pragma unroll
                for (int p = 0; p < 4; p++) {
                    mma16816(sc[2 * p],     qf[ks], kb[p][0], kb[p][1]);
                    mma16816(sc[2 * p + 1], qf[ks], kb[p][2], kb[p][3]);
                }
            }
        }

        float tm0 = -INFINITY, tm1 = -INFINITY;
#pragma unroll
        for (int nt = 0; nt < 8; nt++) {
            const int sh = nt * 8 + 2 * t;
            float s0 = ((mk0 >> sh) & 1ull)       ? sc[nt][0] * scale : -1.0e9f;
            float s1 = ((mk0 >> (sh + 1)) & 1ull) ? sc[nt][1] * scale : -1.0e9f;
            float s2 = ((mk1 >> sh) & 1ull)       ? sc[nt][2] * scale : -1.0e9f;
            float s3 = ((mk1 >> (sh + 1)) & 1ull) ? sc[nt][3] * scale : -1.0e9f;
            sc[nt][0] = s0; sc[nt][1] = s1; sc[nt][2] = s2; sc[nt][3] = s3;
            tm0 = fmaxf(tm0, fmaxf(s0, s1));
            tm1 = fmaxf(tm1, fmaxf(s2, s3));
        }
        tm0 = fmaxf(tm0, __shfl_xor_sync(0xffffffffu, tm0, 1));
        tm0 = fmaxf(tm0, __shfl_xor_sync(0xffffffffu, tm0, 2));
        tm1 = fmaxf(tm1, __shfl_xor_sync(0xffffffffu, tm1, 1));
        tm1 = fmaxf(tm1, __shfl_xor_sync(0xffffffffu, tm1, 2));

        float mn0 = fmaxf(m0, tm0), mn1 = fmaxf(m1, tm1);
        float c0 = __expf(m0 - mn0), c1 = __expf(m1 - mn1);
        m0 = mn0; m1 = mn1;
        l0 *= c0; l1 *= c1;
#pragma unroll
        for (int nt = 0; nt < 16; nt++) {
            accz[nt][0] *= c0; accz[nt][1] *= c0;
            accz[nt][2] *= c1; accz[nt][3] *= c1;
        }

        const float b0l = mn0 * LOG2E, b1l = mn1 * LOG2E;
        unsigned pf[4][4];
#pragma unroll
        for (int nt = 0; nt < 8; nt++) {
            float x0 = fmaf(sc[nt][0], LOG2E, -b0l);
            float x1 = fmaf(sc[nt][1], LOG2E, -b0l);
            float x2 = fmaf(sc[nt][2], LOG2E, -b1l);
            float x3 = fmaf(sc[nt][3], LOG2E, -b1l);
            unsigned e01 = ex2_f16x2(x0, x1);
            unsigned e23 = ex2_f16x2(x2, x3);
            float2 f01 = __half22float2(*(__half2*)&e01);
            float2 f23 = __half22float2(*(__half2*)&e23);
            l0 += f01.x + f01.y;
            l1 += f23.x + f23.y;
            pf[nt >> 1][(nt & 1) * 2 + 0] = e01;
            pf[nt >> 1][(nt & 1) * 2 + 1] = e23;
        }

        {
            unsigned vbase = smb + (AOFF_V + buf * 64 * VS_STR +
                (lane & 15) * VS_STR + (lane >> 4) * 8) * 2;
#pragma unroll
            for (int kt = 0; kt < 4; kt++) {
#pragma unroll
                for (int p = 0; p < 8; p++) {
                    unsigned vf[4];
                    ldsm4t(vf, vbase + kt * 16 * VS_STR * 2 + p * 32);
                    mma16816(accz[2 * p],     pf[kt], vf[0], vf[1]);
                    mma16816(accz[2 * p + 1], pf[kt], vf[2], vf[3]);
                }
            }
        }
    }

    l0 += __shfl_xor_sync(0xffffffffu, l0, 1);
    l0 += __shfl_xor_sync(0xffffffffu, l0, 2);
    l1 += __shfl_xor_sync(0xffffffffu, l1, 1);
    l1 += __shfl_xor_sync(0xffffffffu, l1, 2);
    float inv0 = 1.0f / l0, inv1 = 1.0f / l1;

    const int row0 = q0 + w * 16 + g;
#pragma unroll
    for (int nt = 0; nt < 16; nt++) {
        int col = nt * 8 + 2 * t;
        __half* d0 = Og + ((size_t)(b * NS + row0)) * ND + h * NK + col;
        *(unsigned*)(d0)          = h2pack(accz[nt][0] * inv0, accz[nt][1] * inv0);
        *(unsigned*)(d0 + 8 * ND) = h2pack(accz[nt][2] * inv1, accz[nt][3] * inv1);
    }
}

// ---------------- fused residual add + LayerNorm (R f16) --------------------
__global__ __launch_bounds__(256) void add_ln_kernel(
    const float* __restrict__ X, const __half* __restrict__ R,
    const float* __restrict__ ga, const float* __restrict__ be,
    float* __restrict__ O, __half* __restrict__ O16)
{
    __shared__ float red1[8];
    __shared__ float red2[8];
    __shared__ float s_mean, s_rstd;
    const int row = blockIdx.x;
    const int tid = threadIdx.x;
    const size_t base = (size_t)row * ND;

    float4 a = *(const float4*)(X + base + tid * 4);
    uint2 rr = *(const uint2*)(R + base + tid * 4);
    float2 ra = __half22float2(*(__half2*)&rr.x);
    float2 rb = __half22float2(*(__half2*)&rr.y);
    float v0 = a.x + ra.x, v1 = a.y + ra.y, v2 = a.z + rb.x, v3 = a.w + rb.y;

    float s = v0 + v1 + v2 + v3;
#pragma unroll
    for (int o = 16; o > 0; o >>= 1) s += __shfl_xor_sync(0xffffffffu, s, o);
    if ((tid & 31) == 0) red1[tid >> 5] = s;
    __syncthreads();
    if (tid == 0) {
        float tt = 0.f;
#pragma unroll
        for (int i = 0; i < 8; i++) tt += red1[i];
        s_mean = tt * (1.0f / ND);
    }
    __syncthreads();
    const float mean = s_mean;
    float d0 = v0 - mean, d1 = v1 - mean, d2 = v2 - mean, d3 = v3 - mean;
    float q = d0 * d0 + d1 * d1 + d2 * d2 + d3 * d3;
#pragma unroll
    for (int o = 16; o > 0; o >>= 1) q += __shfl_xor_sync(0xffffffffu, q, o);
    if ((tid & 31) == 0) red2[tid >> 5] = q;
    __syncthreads();
    if (tid == 0) {
        float tt = 0.f;
#pragma unroll
        for (int i = 0; i < 8; i++) tt += red2[i];
        s_rstd = rsqrtf(tt * (1.0f / ND) + 1e-5f);
    }
    __syncthreads();
    const float rstd = s_rstd;

    float4 g4 = *(const float4*)(ga + tid * 4);
    float4 b4 = *(const float4*)(be + tid * 4);
    float4 o4;
    o4.x = d0 * rstd * g4.x + b4.x;
    o4.y = d1 * rstd * g4.y + b4.y;
    o4.z = d2 * rstd * g4.z + b4.z;
    o4.w = d3 * rstd * g4.w + b4.w;
    *(float4*)(O + base + tid * 4) = o4;
    uint2 hh; hh.x = h2pack(o4.x, o4.y); hh.y = h2pack(o4.z, o4.w);
    *(uint2*)(O16 + base + tid * 4) = hh;
}

// ---------------- launcher ---------------------------------------------------
extern "C" void kernel_launch(void* const* d_in, const int* in_sizes, int n_in,
                              void* d_out, int out_size) {
    (void)in_sizes; (void)n_in; (void)out_size;
    const float* x    = (const float*)d_in[0];
    const int*   mask = (const int*)  d_in[1];
    const float* wq   = (const float*)d_in[2];
    const float* bq   = (const float*)d_in[3];
    const float* wk   = (const float*)d_in[4];
    const float* bk   = (const float*)d_in[5];
    const float* wv   = (const float*)d_in[6];
    const float* bv   = (const float*)d_in[7];
    const float* wo   = (const float*)d_in[8];
    const float* bo   = (const float*)d_in[9];
    const float* w1   = (const float*)d_in[10];
    const float* b1   = (const float*)d_in[11];
    const float* w2   = (const float*)d_in[12];
    const float* b2   = (const float*)d_in[13];
    const float* l1g  = (const float*)d_in[14];
    const float* l1b  = (const float*)d_in[15];
    const float* l2g  = (const float*)d_in[16];
    const float* l2b  = (const float*)d_in[17];

    float *px;
    __half *pt1h, *px16, *pq, *pk, *pv, *pao, *ph, *pwtd, *pwtq;
    unsigned long long* pmb;
    cudaGetSymbolAddress((void**)&px,   g_x);
    cudaGetSymbolAddress((void**)&pt1h, g_t1h);
    cudaGetSymbolAddress((void**)&px16, g_x16);
    cudaGetSymbolAddress((void**)&pq,   g_q);
    cudaGetSymbolAddress((void**)&pk,   g_k);
    cudaGetSymbolAddress((void**)&pv,   g_v);
    cudaGetSymbolAddress((void**)&pao,  g_ao);
    cudaGetSymbolAddress((void**)&ph,   g_h);
    cudaGetSymbolAddress((void**)&pwtd, g_wtd);
    cudaGetSymbolAddress((void**)&pwtq, g_wtq);
    cudaGetSymbolAddress((void**)&pmb,  g_mbits);

    cudaFuncSetAttribute(gemm_v4, cudaFuncAttributeMaxDynamicSharedMemorySize, GEMM_SMEM_BYTES);
    cudaFuncSetAttribute(attn_f16, cudaFuncAttributeMaxDynamicSharedMemorySize, ATTN_SMEM_BYTES);

    tr_dense<<<dim3(32, 32, 12), dim3(32, 8)>>>(wo, w1, w2, pwtd);
    tr_qkv  <<<dim3(4,  32, 96), dim3(32, 8)>>>(wq, wk, wv, pwtq);
    prep_mask_bits<<<((size_t)NB * NS * NS / 64) / 256, 256>>>((const int4*)mask, pmb);

    cvt_in<<<(NM * ND / 4) / 256, 256>>>((const float4*)x, (uint2*)px16);

    const dim3 ggrid(ND / 128, NM / 128);
    const dim3 gqkv (ND / 128, NM / 128, 3);

    for (int l = 0; l < NL; l++) {
        const size_t vof = (size_t)l * ND;
        const size_t qb  = (size_t)l * NH * NK;

        gemm_v4<<<gqkv, 128, GEMM_SMEM_BYTES>>>(
            px16, pwtq + (size_t)l * 3 * ND * ND,
            bq + qb, bk + qb, bv + qb,
            pq, pk, pv, 2);

        attn_f16<<<dim3(NS / 128, NB * NH), 256, ATTN_SMEM_BYTES>>>(
            pq, pk, pv, pmb, pao);

        gemm_v4<<<ggrid, 128, GEMM_SMEM_BYTES>>>(
            pao, pwtd + (size_t)(l * 3 + 0) * ND * ND,
            bo + vof, (float*)0, (float*)0, pt1h, (__half*)0, (__half*)0, 0);
        add_ln_kernel<<<NM, 256>>>((l == 0) ? x : px, pt1h,
                                   l1g + vof, l1b + vof, px, px16);

        gemm_v4<<<ggrid, 128, GEMM_SMEM_BYTES>>>(
            px16, pwtd + (size_t)(l * 3 + 1) * ND * ND,
            b1 + vof, (float*)0, (float*)0, ph, (__half*)0, (__half*)0, 1);
        gemm_v4<<<ggrid, 128, GEMM_SMEM_BYTES>>>(
            ph, pwtd + (size_t)(l * 3 + 2) * ND * ND,
            b2 + vof, (float*)0, (float*)0, pt1h, (__half*)0, (__half*)0, 0);

        float* dst = (l == NL - 1) ? (float*)d_out : px;
        add_ln_kernel<<<NM, 256>>>(px, pt1h, l2g + vof, l2b + vof, dst, px16);
    }
}

// round 17
// speedup vs baseline: 1.0600x; 1.0082x over previous
#include <cuda_runtime.h>
#include <cuda_fp16.h>
#include <math.h>
#include <stdint.h>

#define NB 4
#define NS 2048
#define ND 1024
#define NH 8
#define NK 128
#define NL 4
#define NM (NB*NS)

// ---------------- scratch ----------------------------------------------------
__device__ __half g_t1h[NM*ND];
__device__ __half g_x16[NM*ND];
__device__ __half g_q  [NM*ND];
__device__ __half g_k  [NM*ND];
__device__ __half g_v  [NM*ND];
__device__ __half g_ao [NM*ND];
__device__ __half g_h  [NM*ND];
__device__ __half g_wtd[12*ND*ND];
__device__ __half g_wtq[12*ND*ND];
__device__ unsigned long long g_mbits[(size_t)NB*NS*NS/64];

// ---------------- helpers ----------------------------------------------------
__device__ __forceinline__ float gelu_exact(float x) {
    return 0.5f * x * (1.0f + erff(x * 0.7071067811865476f));
}
__device__ __forceinline__ unsigned sptr(const void* p) {
    return (unsigned)__cvta_generic_to_shared(p);
}
__device__ __forceinline__ unsigned h2pack(float x, float y) {
    __half2 h = __floats2half2_rn(x, y);
    return *(unsigned*)&h;
}
__device__ __forceinline__ unsigned ex2_f16x2(float x, float y) {
    __half2 h = __floats2half2_rn(x, y);
    unsigned r;
    asm("ex2.approx.f16x2 %0, %1;" : "=r"(r) : "r"(*(unsigned*)&h));
    return r;
}
__device__ __forceinline__ void ldsm4(unsigned r[4], unsigned a) {
    asm volatile("ldmatrix.sync.aligned.m8n8.x4.shared.b16 {%0,%1,%2,%3}, [%4];\n"
        : "=r"(r[0]), "=r"(r[1]), "=r"(r[2]), "=r"(r[3]) : "r"(a));
}
__device__ __forceinline__ void ldsm4t(unsigned r[4], unsigned a) {
    asm volatile("ldmatrix.sync.aligned.m8n8.x4.trans.shared.b16 {%0,%1,%2,%3}, [%4];\n"
        : "=r"(r[0]), "=r"(r[1]), "=r"(r[2]), "=r"(r[3]) : "r"(a));
}
__device__ __forceinline__ void mma16816(float c[4], const unsigned a[4],
                                         unsigned b0, unsigned b1) {
    asm volatile("mma.sync.aligned.m16n8k16.row.col.f32.f16.f16.f32 "
        "{%0,%1,%2,%3}, {%4,%5,%6,%7}, {%8,%9}, {%0,%1,%2,%3};\n"
        : "+f"(c[0]), "+f"(c[1]), "+f"(c[2]), "+f"(c[3])
        : "r"(a[0]), "r"(a[1]), "r"(a[2]), "r"(a[3]), "r"(b0), "r"(b1));
}
#define CP16(dst, src) \
    asm volatile("cp.async.cg.shared.global [%0], [%1], 16;" :: "r"(dst), "l"(src) : "memory")
#define CP_COMMIT() asm volatile("cp.async.commit_group;" ::: "memory")

// convert-only: x f32 -> f16 (layer-0 LN reads x f32 directly)
__global__ void cvt_in(const float4* __restrict__ s, uint2* __restrict__ dh) {
    int i = blockIdx.x * blockDim.x + threadIdx.x;
    float4 v = s[i];
    uint2 hh; hh.x = h2pack(v.x, v.y); hh.y = h2pack(v.z, v.w);
    dh[i] = hh;
}

__global__ void prep_mask_bits(const int4* __restrict__ m,
                               unsigned long long* __restrict__ o) {
    size_t i = (size_t)blockIdx.x * blockDim.x + threadIdx.x;
    const int4* p = m + i * 16;
    unsigned long long bits = 0;
#pragma unroll
    for (int j = 0; j < 16; j++) {
        int4 v = p[j];
        bits |= (unsigned long long)(v.x != 0) << (j * 4 + 0);
        bits |= (unsigned long long)(v.y != 0) << (j * 4 + 1);
        bits |= (unsigned long long)(v.z != 0) << (j * 4 + 2);
        bits |= (unsigned long long)(v.w != 0) << (j * 4 + 3);
    }
    o[i] = bits;
}

// ---------------- weight transposes ------------------------------------------
__global__ void tr_dense(const float* __restrict__ wo, const float* __restrict__ w1,
                         const float* __restrict__ w2, __half* __restrict__ dst) {
    __shared__ float tile[32][33];
    int z = blockIdx.z, l = z / 3, which = z % 3;
    const float* W = (which == 0 ? wo : which == 1 ? w1 : w2) + (size_t)l * ND * ND;
    __half* D = dst + (size_t)z * ND * ND;
    int n0 = blockIdx.x * 32, k0 = blockIdx.y * 32;
    int tx = threadIdx.x, ty = threadIdx.y;
#pragma unroll
    for (int i = 0; i < 32; i += 8)
        tile[ty + i][tx] = W[(size_t)(k0 + ty + i) * ND + n0 + tx];
    __syncthreads();
#pragma unroll
    for (int i = 0; i < 32; i += 8)
        D[(size_t)(n0 + ty + i) * ND + k0 + tx] = __float2half_rn(tile[tx][ty + i]);
}

__global__ void tr_qkv(const float* __restrict__ wq, const float* __restrict__ wk,
                       const float* __restrict__ wv, __half* __restrict__ dst) {
    __shared__ float tile[32][33];
    int z = blockIdx.z;
    int l = z / 24, rem = z % 24, sel = rem / 8, h = rem % 8;
    const float* W = (sel == 0 ? wq : sel == 1 ? wk : wv) + (size_t)(l * NH + h) * ND * NK;
    __half* D = dst + (size_t)((l * 3 + sel) * 8 + h) * NK * ND;
    int n0 = blockIdx.x * 32, k0 = blockIdx.y * 32;
    int tx = threadIdx.x, ty = threadIdx.y;
#pragma unroll
    for (int i = 0; i < 32; i += 8)
        tile[ty + i][tx] = W[(size_t)(k0 + ty + i) * NK + n0 + tx];
    __syncthreads();
#pragma unroll
    for (int i = 0; i < 32; i += 8)
        D[(size_t)(n0 + ty + i) * ND + k0 + tx] = __float2half_rn(tile[tx][ty + i]);
}

// ============================================================================
// GEMM v4 (proven): block 128x128, 4 warps, warp 64x64, K-chunk 32,
// 3-stage cp.async pipeline, XOR-swizzled 64B rows. All outputs f16.
// mode: 0 = plain half, 1 = half + gelu, 2 = qkv scatter
// ============================================================================
#define BK 32
#define STG 3
#define ASZ (128*BK)
#define NCH (ND/BK)
#define GEMM_SMEM_BYTES (STG*2*ASZ*2)

__global__ __launch_bounds__(128, 2) void gemm_v4(
    const __half* __restrict__ A, const __half* __restrict__ BtBase,
    const float* __restrict__ bias0, const float* __restrict__ bias1,
    const float* __restrict__ bias2,
    __half* __restrict__ Ch0, __half* __restrict__ Ch1,
    __half* __restrict__ Ch2, int mode)
{
    extern __shared__ __half smh[];
    __half* sA = smh;
    __half* sB = smh + STG * ASZ;

    const int tid = threadIdx.x, lane = tid & 31, wid = tid >> 5;
    const int wm = wid >> 1, wn = wid & 1, g = lane >> 2, t = lane & 3;
    const int m0 = blockIdx.y * 128, n0 = blockIdx.x * 128;

    const int sel = blockIdx.z;
    const __half* Bt = BtBase + (size_t)sel * ND * ND;
    const float* bias = (sel == 0) ? bias0 : (sel == 1) ? bias1 : bias2;
    __half* Ch = (sel == 0) ? Ch0 : (sel == 1) ? Ch1 : Ch2;

    float c[4][8][4];
#pragma unroll
    for (int mt = 0; mt < 4; mt++)
#pragma unroll
        for (int nt = 0; nt < 8; nt++)
#pragma unroll
            for (int i = 0; i < 4; i++) c[mt][nt][i] = 0.f;

    const int lr = tid >> 2;
    const int lu = tid & 3;
    const unsigned sA0 = sptr(sA), sB0 = sptr(sB);

    const int arow = wm * 64 + (lane & 15);
    const int axor = (arow >> 1) & 3;
    const int ahi  = lane >> 4;
    const int brow = (lane >> 4) * 8 + (lane & 7);
    const int bxor = (brow >> 1) & 3;
    const int bhi  = (lane >> 3) & 1;

#define LOAD_CHUNK(ck, st) do {                                               \
    int _k0 = (ck) * BK;                                                      \
    _Pragma("unroll")                                                         \
    for (int _i = 0; _i < 4; _i++) {                                          \
        int _r = lr + _i * 32;                                                \
        unsigned _sw = ((unsigned)(lu ^ ((_r >> 1) & 3))) * 16;               \
        CP16(sA0 + (st) * ASZ * 2 + _r * 64 + _sw,                            \
             A + (size_t)(m0 + _r) * ND + _k0 + lu * 8);                      \
        CP16(sB0 + (st) * ASZ * 2 + _r * 64 + _sw,                            \
             Bt + (size_t)(n0 + _r) * ND + _k0 + lu * 8);                     \
    }                                                                         \
    CP_COMMIT();                                                              \
} while (0)

    LOAD_CHUNK(0, 0);
    LOAD_CHUNK(1, 1);

    int st = 0;
    for (int ck = 0; ck < NCH; ck++) {
        if (ck + 2 < NCH) {
            asm volatile("cp.async.wait_group 1;" ::: "memory");
        } else {
            asm volatile("cp.async.wait_group 0;" ::: "memory");
        }
        __syncthreads();
        if (ck + 2 < NCH) {
            int st2 = st + 2; if (st2 >= STG) st2 -= STG;
            LOAD_CHUNK(ck + 2, st2);
        }

        unsigned abuf = sA0 + st * ASZ * 2;
        unsigned bbuf = sB0 + st * ASZ * 2;
#pragma unroll
        for (int ks = 0; ks < 2; ks++) {
            unsigned akoff = ((unsigned)((ks * 2 + ahi) ^ axor)) * 16;
            unsigned a[4][4];
#pragma unroll
            for (int mt = 0; mt < 4; mt++)
                ldsm4(a[mt], abuf + (arow + mt * 16) * 64 + akoff);
            unsigned bkoff = ((unsigned)((ks * 2 + bhi) ^ bxor)) * 16;
#pragma unroll
            for (int p = 0; p < 4; p++) {
                unsigned bf[4];
                ldsm4(bf, bbuf + (brow + wn * 64 + p * 16) * 64 + bkoff);
#pragma unroll
                for (int mt = 0; mt < 4; mt++) {
                    mma16816(c[mt][2 * p],     a[mt], bf[0], bf[1]);
                    mma16816(c[mt][2 * p + 1], a[mt], bf[2], bf[3]);
                }
            }
        }
        if (++st >= STG) st -= STG;
    }

#pragma unroll
    for (int mt = 0; mt < 4; mt++) {
        int r0 = m0 + wm * 64 + mt * 16 + g;
#pragma unroll
        for (int nt = 0; nt < 8; nt++) {
            int col = n0 + wn * 64 + nt * 8 + 2 * t;
            float b0 = bias[col], b1 = bias[col + 1];
            float v0 = c[mt][nt][0] + b0, v1 = c[mt][nt][1] + b1;
            float v2 = c[mt][nt][2] + b0, v3 = c[mt][nt][3] + b1;
            if (mode == 1) {
                v0 = gelu_exact(v0); v1 = gelu_exact(v1);
                v2 = gelu_exact(v2); v3 = gelu_exact(v3);
            }
            if (mode == 2) {
                int head = col >> 7, within = col & 127;
                int bb0 = r0 >> 11, s0 = r0 & (NS - 1);
                __half* d0 = Ch + ((size_t)(bb0 * NH + head) * NS + s0) * NK + within;
                *(unsigned*)(d0)          = h2pack(v0, v1);
                *(unsigned*)(d0 + 8 * NK) = h2pack(v2, v3);
            } else {
                *(unsigned*)(Ch + (size_t)r0 * ND + col)       = h2pack(v0, v1);
                *(unsigned*)(Ch + (size_t)(r0 + 8) * ND + col) = h2pack(v2, v3);
            }
        }
    }
}

// ============================================================================
// Flash attention (proven): 8 warps x (16x64), register P, Q in registers,
// K/V double-buffered cp.async, ONE barrier/tile, f16x2 exp, bitmask mask.
// ============================================================================
#define QS_STR 136
#define KS_STR 136
#define VS_STR 136
#define AOFF_Q 0
#define AOFF_K (128*QS_STR)
#define AOFF_V (AOFF_K + 2*64*KS_STR)
#define ATTN_SMEM_BYTES ((AOFF_V + 2*64*VS_STR)*2)
#define MW (NS/64)

__global__ __launch_bounds__(256) void attn_f16(
    const __half* __restrict__ Qg, const __half* __restrict__ Kg,
    const __half* __restrict__ Vg, const unsigned long long* __restrict__ Mb,
    __half* __restrict__ Og)
{
    extern __shared__ __half smh[];
    const int tid = threadIdx.x, lane = tid & 31, w = tid >> 5;
    const int g = lane >> 2, t = lane & 3;
    const int bh = blockIdx.y, b = bh >> 3, h = bh & 7;
    const int q0 = blockIdx.x * 128;
    const unsigned smb = sptr(smh);

#define ATTN_LOAD_KV(tnext, buf) do {                                         \
    const __half* _Kb = Kg + ((size_t)bh * NS + (tnext)) * NK;                \
    const __half* _Vb = Vg + ((size_t)bh * NS + (tnext)) * NK;                \
    _Pragma("unroll")                                                         \
    for (int _i = 0; _i < 4; _i++) {                                          \
        int _u = tid + _i * 256;                                              \
        int _r = _u >> 4, _c = (_u & 15) * 8;                                 \
        CP16(smb + (AOFF_K + (buf) * 64 * KS_STR + _r * KS_STR + _c) * 2,     \
             _Kb + _r * NK + _c);                                             \
        CP16(smb + (AOFF_V + (buf) * 64 * VS_STR + _r * VS_STR + _c) * 2,     \
             _Vb + _r * NK + _c);                                             \
    }                                                                         \
    CP_COMMIT();                                                              \
} while (0)

    ATTN_LOAD_KV(0, 0);

    const __half* Qb = Qg + ((size_t)bh * NS + q0) * NK;
#pragma unroll
    for (int i = 0; i < 8; i++) {
        int idx = tid + i * 256;
        int r = idx >> 4, c8 = (idx & 15) * 8;
        *(uint4*)&smh[AOFF_Q + r * QS_STR + c8] = *(const uint4*)(Qb + (size_t)r * NK + c8);
    }
    __syncthreads();

    unsigned qf[8][4];
    {
        unsigned qbase = smb + (AOFF_Q + (w * 16 + (lane & 15)) * QS_STR + (lane >> 4) * 8) * 2;
#pragma unroll
        for (int ks = 0; ks < 8; ks++) ldsm4(qf[ks], qbase + ks * 32);
    }

    float accz[16][4];
#pragma unroll
    for (int nt = 0; nt < 16; nt++)
#pragma unroll
        for (int i = 0; i < 4; i++) accz[nt][i] = 0.f;

    float m0 = -INFINITY, m1 = -INFINITY, l0 = 0.f, l1 = 0.f;
    const float scale = 0.08838834764831845f;
    const float LOG2E = 1.4426950408889634f;

    const int rl = w * 16 + g;
    const unsigned long long* mb0 = Mb + ((size_t)b * NS + q0 + rl) * MW;
    const unsigned long long* mb1 = mb0 + 8 * MW;

    for (int tix = 0; tix < NS / 64; tix++) {
        const int buf = tix & 1;

        const unsigned long long mk0 = mb0[tix];
        const unsigned long long mk1 = mb1[tix];

        asm volatile("cp.async.wait_group 0;" ::: "memory");
        __syncthreads();
        if (tix + 1 < NS / 64) ATTN_LOAD_KV((tix + 1) * 64, buf ^ 1);

        float sc[8][4];
#pragma unroll
        for (int nt = 0; nt < 8; nt++)
#pragma unroll
            for (int i = 0; i < 4; i++) sc[nt][i] = 0.f;
        {
            unsigned kbase = smb + (AOFF_K + buf * 64 * KS_STR +
                ((lane >> 4) * 8 + (lane & 7)) * KS_STR + ((lane >> 3) & 1) * 8) * 2;
#pragma unroll
            for (int ks = 0; ks < 8; ks++) {
                unsigned kb[4][4];
#pragma unroll
                for (int p = 0; p < 4; p++)
                    ldsm4(kb[p], kbase + p * 16 * KS_STR * 2 + ks * 32);
#pragma unroll
                for (int p = 0; p < 4; p++) {
                    mma16816(sc[2 * p],     qf[ks], kb[p][0], kb[p][1]);
                    mma16816(sc[2 * p + 1], qf[ks], kb[p][2], kb[p][3]);
                }
            }
        }

        float tm0 = -INFINITY, tm1 = -INFINITY;
#pragma unroll
        for (int nt = 0; nt < 8; nt++) {
            const int sh = nt * 8 + 2 * t;
            float s0 = ((mk0 >> sh) & 1ull)       ? sc[nt][0] * scale : -1.0e9f;
            float s1 = ((mk0 >> (sh + 1)) & 1ull) ? sc[nt][1] * scale : -1.0e9f;
            float s2 = ((mk1 >> sh) & 1ull)       ? sc[nt][2] * scale : -1.0e9f;
            float s3 = ((mk1 >> (sh + 1)) & 1ull) ? sc[nt][3] * scale : -1.0e9f;
            sc[nt][0] = s0; sc[nt][1] = s1; sc[nt][2] = s2; sc[nt][3] = s3;
            tm0 = fmaxf(tm0, fmaxf(s0, s1));
            tm1 = fmaxf(tm1, fmaxf(s2, s3));
        }
        tm0 = fmaxf(tm0, __shfl_xor_sync(0xffffffffu, tm0, 1));
        tm0 = fmaxf(tm0, __shfl_xor_sync(0xffffffffu, tm0, 2));
        tm1 = fmaxf(tm1, __shfl_xor_sync(0xffffffffu, tm1, 1));
        tm1 = fmaxf(tm1, __shfl_xor_sync(0xffffffffu, tm1, 2));

        float mn0 = fmaxf(m0, tm0), mn1 = fmaxf(m1, tm1);
        float c0 = __expf(m0 - mn0), c1 = __expf(m1 - mn1);
        m0 = mn0; m1 = mn1;
        l0 *= c0; l1 *= c1;
#pragma unroll
        for (int nt = 0; nt < 16; nt++) {
            accz[nt][0] *= c0; accz[nt][1] *= c0;
            accz[nt][2] *= c1; accz[nt][3] *= c1;
        }

        const float b0l = mn0 * LOG2E, b1l = mn1 * LOG2E;
        unsigned pf[4][4];
#pragma unroll
        for (int nt = 0; nt < 8; nt++) {
            float x0 = fmaf(sc[nt][0], LOG2E, -b0l);
            float x1 = fmaf(sc[nt][1], LOG2E, -b0l);
            float x2 = fmaf(sc[nt][2], LOG2E, -b1l);
            float x3 = fmaf(sc[nt][3], LOG2E, -b1l);
            unsigned e01 = ex2_f16x2(x0, x1);
            unsigned e23 = ex2_f16x2(x2, x3);
            float2 f01 = __half22float2(*(__half2*)&e01);
            float2 f23 = __half22float2(*(__half2*)&e23);
            l0 += f01.x + f01.y;
            l1 += f23.x + f23.y;
            pf[nt >> 1][(nt & 1) * 2 + 0] = e01;
            pf[nt >> 1][(nt & 1) * 2 + 1] = e23;
        }

        {
            unsigned vbase = smb + (AOFF_V + buf * 64 * VS_STR +
                (lane & 15) * VS_STR + (lane >> 4) * 8) * 2;
#pragma unroll
            for (int kt = 0; kt < 4; kt++) {
#pragma unroll
                for (int p = 0; p < 8; p++) {
                    unsigned vf[4];
                    ldsm4t(vf, vbase + kt * 16 * VS_STR * 2 + p * 32);
                    mma16816(accz[2 * p],     pf[kt], vf[0], vf[1]);
                    mma16816(accz[2 * p + 1], pf[kt], vf[2], vf[3]);
                }
            }
        }
    }

    l0 += __shfl_xor_sync(0xffffffffu, l0, 1);
    l0 += __shfl_xor_sync(0xffffffffu, l0, 2);
    l1 += __shfl_xor_sync(0xffffffffu, l1, 1);
    l1 += __shfl_xor_sync(0xffffffffu, l1, 2);
    float inv0 = 1.0f / l0, inv1 = 1.0f / l1;

    const int row0 = q0 + w * 16 + g;
#pragma unroll
    for (int nt = 0; nt < 16; nt++) {
        int col = nt * 8 + 2 * t;
        __half* d0 = Og + ((size_t)(b * NS + row0)) * ND + h * NK + col;
        *(unsigned*)(d0)          = h2pack(accz[nt][0] * inv0, accz[nt][1] * inv0);
        *(unsigned*)(d0 + 8 * ND) = h2pack(accz[nt][2] * inv1, accz[nt][3] * inv1);
    }
}

// ---------------- fused residual add + LayerNorm ----------------------------
// X: f16 (xh) or f32 (xf, layer 0). Writes O16 f16 always; Of f32 if non-null.
__global__ __launch_bounds__(256) void add_ln_kernel(
    const __half* __restrict__ Xh, const float* __restrict__ Xf,
    const __half* __restrict__ R,
    const float* __restrict__ ga, const float* __restrict__ be,
    float* __restrict__ Of, __half* __restrict__ O16)
{
    __shared__ float red1[8];
    __shared__ float red2[8];
    __shared__ float s_mean, s_rstd;
    const int row = blockIdx.x;
    const int tid = threadIdx.x;
    const size_t base = (size_t)row * ND;

    float v0, v1, v2, v3;
    if (Xf) {
        float4 a = *(const float4*)(Xf + base + tid * 4);
        v0 = a.x; v1 = a.y; v2 = a.z; v3 = a.w;
    } else {
        uint2 xx = *(const uint2*)(Xh + base + tid * 4);
        float2 xa = __half22float2(*(__half2*)&xx.x);
        float2 xb = __half22float2(*(__half2*)&xx.y);
        v0 = xa.x; v1 = xa.y; v2 = xb.x; v3 = xb.y;
    }
    uint2 rr = *(const uint2*)(R + base + tid * 4);
    float2 ra = __half22float2(*(__half2*)&rr.x);
    float2 rb = __half22float2(*(__half2*)&rr.y);
    v0 += ra.x; v1 += ra.y; v2 += rb.x; v3 += rb.y;

    float s = v0 + v1 + v2 + v3;
#pragma unroll
    for (int o = 16; o > 0; o >>= 1) s += __shfl_xor_sync(0xffffffffu, s, o);
    if ((tid & 31) == 0) red1[tid >> 5] = s;
    __syncthreads();
    if (tid == 0) {
        float tt = 0.f;
#pragma unroll
        for (int i = 0; i < 8; i++) tt += red1[i];
        s_mean = tt * (1.0f / ND);
    }
    __syncthreads();
    const float mean = s_mean;
    float d0 = v0 - mean, d1 = v1 - mean, d2 = v2 - mean, d3 = v3 - mean;
    float q = d0 * d0 + d1 * d1 + d2 * d2 + d3 * d3;
#pragma unroll
    for (int o = 16; o > 0; o >>= 1) q += __shfl_xor_sync(0xffffffffu, q, o);
    if ((tid & 31) == 0) red2[tid >> 5] = q;
    __syncthreads();
    if (tid == 0) {
        float tt = 0.f;
#pragma unroll
        for (int i = 0; i < 8; i++) tt += red2[i];
        s_rstd = rsqrtf(tt * (1.0f / ND) + 1e-5f);
    }
    __syncthreads();
    const float rstd = s_rstd;

    float4 g4 = *(const float4*)(ga + tid * 4);
    float4 b4 = *(const float4*)(be + tid * 4);
    float o0 = d0 * rstd * g4.x + b4.x;
    float o1 = d1 * rstd * g4.y + b4.y;
    float o2 = d2 * rstd * g4.z + b4.z;
    float o3 = d3 * rstd * g4.w + b4.w;
    if (Of) {
        float4 o4 = make_float4(o0, o1, o2, o3);
        *(float4*)(Of + base + tid * 4) = o4;
    }
    uint2 hh; hh.x = h2pack(o0, o1); hh.y = h2pack(o2, o3);
    *(uint2*)(O16 + base + tid * 4) = hh;
}

// ---------------- launcher ---------------------------------------------------
extern "C" void kernel_launch(void* const* d_in, const int* in_sizes, int n_in,
                              void* d_out, int out_size) {
    (void)in_sizes; (void)n_in; (void)out_size;
    const float* x    = (const float*)d_in[0];
    const int*   mask = (const int*)  d_in[1];
    const float* wq   = (const float*)d_in[2];
    const float* bq   = (const float*)d_in[3];
    const float* wk   = (const float*)d_in[4];
    const float* bk   = (const float*)d_in[5];
    const float* wv   = (const float*)d_in[6];
    const float* bv   = (const float*)d_in[7];
    const float* wo   = (const float*)d_in[8];
    const float* bo   = (const float*)d_in[9];
    const float* w1   = (const float*)d_in[10];
    const float* b1   = (const float*)d_in[11];
    const float* w2   = (const float*)d_in[12];
    const float* b2   = (const float*)d_in[13];
    const float* l1g  = (const float*)d_in[14];
    const float* l1b  = (const float*)d_in[15];
    const float* l2g  = (const float*)d_in[16];
    const float* l2b  = (const float*)d_in[17];

    __half *pt1h, *px16, *pq, *pk, *pv, *pao, *ph, *pwtd, *pwtq;
    unsigned long long* pmb;
    cudaGetSymbolAddress((void**)&pt1h, g_t1h);
    cudaGetSymbolAddress((void**)&px16, g_x16);
    cudaGetSymbolAddress((void**)&pq,   g_q);
    cudaGetSymbolAddress((void**)&pk,   g_k);
    cudaGetSymbolAddress((void**)&pv,   g_v);
    cudaGetSymbolAddress((void**)&pao,  g_ao);
    cudaGetSymbolAddress((void**)&ph,   g_h);
    cudaGetSymbolAddress((void**)&pwtd, g_wtd);
    cudaGetSymbolAddress((void**)&pwtq, g_wtq);
    cudaGetSymbolAddress((void**)&pmb,  g_mbits);

    cudaFuncSetAttribute(gemm_v4, cudaFuncAttributeMaxDynamicSharedMemorySize, GEMM_SMEM_BYTES);
    cudaFuncSetAttribute(attn_f16, cudaFuncAttributeMaxDynamicSharedMemorySize, ATTN_SMEM_BYTES);

    tr_dense<<<dim3(32, 32, 12), dim3(32, 8)>>>(wo, w1, w2, pwtd);
    tr_qkv  <<<dim3(4,  32, 96), dim3(32, 8)>>>(wq, wk, wv, pwtq);
    prep_mask_bits<<<((size_t)NB * NS * NS / 64) / 256, 256>>>((const int4*)mask, pmb);

    cvt_in<<<(NM * ND / 4) / 256, 256>>>((const float4*)x, (uint2*)px16);

    const dim3 ggrid(ND / 128, NM / 128);
    const dim3 gqkv (ND / 128, NM / 128, 3);

    for (int l = 0; l < NL; l++) {
        const size_t vof = (size_t)l * ND;
        const size_t qb  = (size_t)l * NH * NK;

        gemm_v4<<<gqkv, 128, GEMM_SMEM_BYTES>>>(
            px16, pwtq + (size_t)l * 3 * ND * ND,
            bq + qb, bk + qb, bv + qb,
            pq, pk, pv, 2);

        attn_f16<<<dim3(NS / 128, NB * NH), 256, ATTN_SMEM_BYTES>>>(
            pq, pk, pv, pmb, pao);

        gemm_v4<<<ggrid, 128, GEMM_SMEM_BYTES>>>(
            pao, pwtd + (size_t)(l * 3 + 0) * ND * ND,
            bo + vof, (float*)0, (float*)0, pt1h, (__half*)0, (__half*)0, 0);
        // residual X: layer 0 reads f32 input, else f16 LN output stream
        add_ln_kernel<<<NM, 256>>>((l == 0) ? (const __half*)0 : px16,
                                   (l == 0) ? x : (const float*)0,
                                   pt1h, l1g + vof, l1b + vof,
                                   (float*)0, px16);

        gemm_v4<<<ggrid, 128, GEMM_SMEM_BYTES>>>(
            px16, pwtd + (size_t)(l * 3 + 1) * ND * ND,
            b1 + vof, (float*)0, (float*)0, ph, (__half*)0, (__half*)0, 1);
        gemm_v4<<<ggrid, 128, GEMM_SMEM_BYTES>>>(
            ph, pwtd + (size_t)(l * 3 + 2) * ND * ND,
            b2 + vof, (float*)0, (float*)0, pt1h, (__half*)0, (__half*)0, 0);

        float* dst = (l == NL - 1) ? (float*)d_out : (float*)0;
        add_ln_kernel<<<NM, 256>>>(px16, (const float*)0, pt1h,
                                   l2g + vof, l2b + vof, dst, px16);
    }
}